// round 4
// baseline (speedup 1.0000x reference)
#include <cuda_runtime.h>

#define Bn 32
#define Tn 2048
#define Fn 2048
#define DQn 1024
#define UNITSn 1024
#define HALFn 1024      // F/2
#define CONCATn 2048    // HALF + DQ
#define SEG 16          // T segments per batch
#define TS (Tn / SEG)   // 128 rows per segment block
#define WPB 8           // warps per block (256 threads)
#define RPW (TS / WPB)  // 16 rows per warp

// Scratch (allocation-free rule: __device__ globals)
__device__ float g_w[CONCATn];               // W1 @ V
__device__ float g_qb[Bn];                   // query[b]·w[1024:] + b1·V + bV
__device__ float g_score[Bn * Tn];           // raw scores
__device__ float g_partial[Bn * SEG * Fn];   // per-seg ctx partials (scale e^{m_seg})
__device__ float g_m[Bn * SEG];              // per-segment max
__device__ float g_Z[Bn * SEG];              // per-segment exp-sum at m_seg

// ---------------------------------------------------------------------------
// K1: w[c] = sum_u W1[c,u] * V[u]   (one warp per output c)
// ---------------------------------------------------------------------------
__global__ void k_w(const float* __restrict__ W1, const float* __restrict__ V) {
    int warp = (blockIdx.x * blockDim.x + threadIdx.x) >> 5;
    int lane = threadIdx.x & 31;
    if (warp >= CONCATn) return;
    const float4* row = reinterpret_cast<const float4*>(W1 + (size_t)warp * UNITSn);
    const float4* v4  = reinterpret_cast<const float4*>(V);
    float acc = 0.f;
#pragma unroll
    for (int i = 0; i < UNITSn / 128; i++) {
        float4 a = row[lane + i * 32];
        float4 b = v4[lane + i * 32];
        acc += a.x * b.x + a.y * b.y + a.z * b.z + a.w * b.w;
    }
#pragma unroll
    for (int o = 16; o; o >>= 1) acc += __shfl_xor_sync(0xffffffffu, acc, o);
    if (lane == 0) g_w[warp] = acc;
}

// ---------------------------------------------------------------------------
// K2: qb[b] = query[b]·w[HALF:] + b1·V + bV   (one warp per batch)
// ---------------------------------------------------------------------------
__global__ void k_qb(const float* __restrict__ query, const float* __restrict__ b1,
                     const float* __restrict__ V, const float* __restrict__ bV) {
    int b = threadIdx.x >> 5;
    int lane = threadIdx.x & 31;
    const float4* q4 = reinterpret_cast<const float4*>(query + (size_t)b * DQn);
    const float4* w4 = reinterpret_cast<const float4*>(g_w + HALFn);
    const float4* b4 = reinterpret_cast<const float4*>(b1);
    const float4* v4 = reinterpret_cast<const float4*>(V);
    float acc = 0.f;
#pragma unroll
    for (int i = 0; i < DQn / 128; i++) {
        float4 q = q4[lane + i * 32];
        float4 w = w4[lane + i * 32];
        acc += q.x * w.x + q.y * w.y + q.z * w.z + q.w * w.w;
        float4 bb = b4[lane + i * 32];
        float4 vv = v4[lane + i * 32];
        acc += bb.x * vv.x + bb.y * vv.y + bb.z * vv.z + bb.w * vv.w;
    }
#pragma unroll
    for (int o = 16; o; o >>= 1) acc += __shfl_xor_sync(0xffffffffu, acc, o);
    if (lane == 0) g_qb[b] = acc + bV[0];
}

// ---------------------------------------------------------------------------
// K3 (k_main): single-pass fused scores + online softmax + full context.
//   Warp-private accumulators, ZERO barriers in the streaming loop,
//   each byte of `values` read exactly once from DRAM into registers.
// ---------------------------------------------------------------------------
__global__ __launch_bounds__(256, 2) void k_main(const float* __restrict__ values) {
    __shared__ float sw[HALFn];            // 4 KB: w[:1024]
    __shared__ float swacc[WPB * HALFn];   // 32 KB: merge buffer (reused 2 passes)
    __shared__ float s_m[WPB], s_Z[WPB];

    int seg = blockIdx.x, b = blockIdx.y;
    int tid = threadIdx.x, warp = tid >> 5, lane = tid & 31;

    for (int i = tid; i < HALFn; i += 256) sw[i] = g_w[i];
    float qb = g_qb[b];
    __syncthreads();

    int tbase = seg * TS;
    const float* base = values + ((size_t)(b * Tn + tbase)) * Fn;
    const float4* w4 = reinterpret_cast<const float4*>(sw);

    float4 a1[8], a2[8];
#pragma unroll
    for (int i = 0; i < 8; i++) {
        a1[i] = make_float4(0.f, 0.f, 0.f, 0.f);
        a2[i] = make_float4(0.f, 0.f, 0.f, 0.f);
    }
    float m = -1e30f, Z = 0.f;

#pragma unroll 1
    for (int r = 0; r < RPW; r++) {
        int row = r * WPB + warp;
        const float4* rp = reinterpret_cast<const float4*>(base + (size_t)row * Fn);

        // load first half into registers
        float4 v1[8];
#pragma unroll
        for (int i = 0; i < 8; i++) v1[i] = rp[lane + 32 * i];

        // dot against w
        float d = 0.f;
#pragma unroll
        for (int i = 0; i < 8; i++) {
            float4 w = w4[lane + 32 * i];
            d += v1[i].x * w.x + v1[i].y * w.y + v1[i].z * w.z + v1[i].w * w.w;
        }
#pragma unroll
        for (int o = 16; o; o >>= 1) d += __shfl_xor_sync(0xffffffffu, d, o);
        float s = d + qb;
        if (lane == 0) g_score[b * Tn + tbase + row] = s;

        // warp-uniform online-max rescale (rare after warmup)
        if (s > m) {
            float c = __expf(m - s);
            m = s;
            Z *= c;
#pragma unroll
            for (int i = 0; i < 8; i++) {
                a1[i].x *= c; a1[i].y *= c; a1[i].z *= c; a1[i].w *= c;
                a2[i].x *= c; a2[i].y *= c; a2[i].z *= c; a2[i].w *= c;
            }
        }
        float e = __expf(s - m);
        Z += e;

        // accumulate both halves
#pragma unroll
        for (int i = 0; i < 8; i++) {
            float4 v2 = rp[256 + lane + 32 * i];
            a1[i].x += e * v1[i].x; a1[i].y += e * v1[i].y;
            a1[i].z += e * v1[i].z; a1[i].w += e * v1[i].w;
            a2[i].x += e * v2.x;    a2[i].y += e * v2.y;
            a2[i].z += e * v2.z;    a2[i].w += e * v2.w;
        }
    }

    // ---- merge 8 warps (two passes through 32 KB smem buffer) ----
    if (lane == 0) { s_m[warp] = m; s_Z[warp] = Z; }
#pragma unroll
    for (int i = 0; i < 8; i++)
        *reinterpret_cast<float4*>(&swacc[warp * HALFn + 4 * (lane + 32 * i)]) = a1[i];
    __syncthreads();

    float mseg = s_m[0];
#pragma unroll
    for (int w = 1; w < WPB; w++) mseg = fmaxf(mseg, s_m[w]);
    float wt[WPB];
    float Zseg = 0.f;
#pragma unroll
    for (int w = 0; w < WPB; w++) {
        wt[w] = __expf(s_m[w] - mseg);
        Zseg += s_Z[w] * wt[w];
    }

    float* part = g_partial + ((size_t)(b * SEG + seg)) * Fn;
    {   // pass 1: first half — thread tid owns cols [4*tid, 4*tid+3]
        float4 rsum = make_float4(0.f, 0.f, 0.f, 0.f);
#pragma unroll
        for (int w = 0; w < WPB; w++) {
            float4 c = *reinterpret_cast<const float4*>(&swacc[w * HALFn + 4 * tid]);
            rsum.x += wt[w] * c.x; rsum.y += wt[w] * c.y;
            rsum.z += wt[w] * c.z; rsum.w += wt[w] * c.w;
        }
        *reinterpret_cast<float4*>(&part[4 * tid]) = rsum;
    }
    __syncthreads();
#pragma unroll
    for (int i = 0; i < 8; i++)
        *reinterpret_cast<float4*>(&swacc[warp * HALFn + 4 * (lane + 32 * i)]) = a2[i];
    __syncthreads();
    {   // pass 2: second half
        float4 rsum = make_float4(0.f, 0.f, 0.f, 0.f);
#pragma unroll
        for (int w = 0; w < WPB; w++) {
            float4 c = *reinterpret_cast<const float4*>(&swacc[w * HALFn + 4 * tid]);
            rsum.x += wt[w] * c.x; rsum.y += wt[w] * c.y;
            rsum.z += wt[w] * c.z; rsum.w += wt[w] * c.w;
        }
        *reinterpret_cast<float4*>(&part[HALFn + 4 * tid]) = rsum;
    }

    if (tid == 0) {
        g_m[b * SEG + seg] = mseg;
        g_Z[b * SEG + seg] = Zseg;
    }
}

// ---------------------------------------------------------------------------
// K4 (k_epi): per-batch stats + combine partials -> ctx, write aw.
//   grid (Bn, 2): y==0 -> context, y==1 -> attention weights.
// ---------------------------------------------------------------------------
__global__ __launch_bounds__(512) void k_epi(float* __restrict__ ctx,
                                             float* __restrict__ aw) {
    int b = blockIdx.x;
    int tid = threadIdx.x;

    // per-batch global stats (cheap, L2-broadcast reads)
    float gm = -1e30f;
#pragma unroll
    for (int s = 0; s < SEG; s++) gm = fmaxf(gm, g_m[b * SEG + s]);
    float Zg = 0.f;
#pragma unroll
    for (int s = 0; s < SEG; s++) Zg += g_Z[b * SEG + s] * __expf(g_m[b * SEG + s] - gm);
    float inv = 1.0f / Zg;

    if (blockIdx.y == 0) {
        // context: 512 threads × float4 = 2048 cols
        float4 a = make_float4(0.f, 0.f, 0.f, 0.f);
#pragma unroll
        for (int s = 0; s < SEG; s++) {
            float w = __expf(g_m[b * SEG + s] - gm) * inv;
            float4 c = *reinterpret_cast<const float4*>(
                &g_partial[((size_t)(b * SEG + s)) * Fn + 4 * tid]);
            a.x += w * c.x; a.y += w * c.y; a.z += w * c.z; a.w += w * c.w;
        }
        *reinterpret_cast<float4*>(&ctx[(size_t)b * Fn + 4 * tid]) = a;
    } else {
        // attention weights: 2048 per batch, float4 per thread
        float4 sc = *reinterpret_cast<const float4*>(&g_score[b * Tn + 4 * tid]);
        float4 r;
        r.x = __expf(sc.x - gm) * inv;
        r.y = __expf(sc.y - gm) * inv;
        r.z = __expf(sc.z - gm) * inv;
        r.w = __expf(sc.w - gm) * inv;
        *reinterpret_cast<float4*>(&aw[b * Tn + 4 * tid]) = r;
    }
}

// ---------------------------------------------------------------------------
extern "C" void kernel_launch(void* const* d_in, const int* in_sizes, int n_in,
                              void* d_out, int out_size) {
    const float* query  = (const float*)d_in[0];
    const float* values = (const float*)d_in[1];
    const float* W1     = (const float*)d_in[2];
    const float* b1     = (const float*)d_in[3];
    const float* V      = (const float*)d_in[4];
    const float* bV     = (const float*)d_in[5];

    float* out = (float*)d_out;
    float* ctx = out;                 // [B, F]   context_vector (32,1,2048)
    float* aw  = out + Bn * Fn;       // [B, T]   attention_weights (32,2048,1)

    k_w<<<CONCATn / 8, 256>>>(W1, V);
    k_qb<<<1, 1024>>>(query, b1, V, bV);
    dim3 g(SEG, Bn);
    k_main<<<g, 256>>>(values);
    dim3 ge(Bn, 2);
    k_epi<<<ge, 512>>>(ctx, aw);
}

// round 5
// speedup vs baseline: 1.2042x; 1.2042x over previous
#include <cuda_runtime.h>

#define Bn 32
#define Tn 2048
#define Fn 2048
#define DQn 1024
#define UNITSn 1024
#define HALFn 1024      // F/2
#define CONCATn 2048    // HALF + DQ
#define SEG 16          // T segments per batch
#define TS (Tn / SEG)   // 128 rows per segment block
#define PAIRS 4         // warp pairs per block (8 warps, 256 threads)
#define RPP (TS / PAIRS) // 32 rows per pair

// Scratch (allocation-free rule: __device__ globals)
__device__ float g_w[CONCATn];               // W1 @ V
__device__ float g_qb[Bn];                   // query[b]·w[1024:] + b1·V + bV
__device__ float g_score[Bn * Tn];           // raw scores
__device__ float g_partial[Bn * SEG * Fn];   // per-seg ctx partials (scale e^{m_seg})
__device__ float g_m[Bn * SEG];              // per-segment max
__device__ float g_Z[Bn * SEG];              // per-segment exp-sum at m_seg

// ---------------------------------------------------------------------------
// K1: w[c] = sum_u W1[c,u] * V[u]   (one warp per output c)
// ---------------------------------------------------------------------------
__global__ void k_w(const float* __restrict__ W1, const float* __restrict__ V) {
    int warp = (blockIdx.x * blockDim.x + threadIdx.x) >> 5;
    int lane = threadIdx.x & 31;
    if (warp >= CONCATn) return;
    const float4* row = reinterpret_cast<const float4*>(W1 + (size_t)warp * UNITSn);
    const float4* v4  = reinterpret_cast<const float4*>(V);
    float acc = 0.f;
#pragma unroll
    for (int i = 0; i < UNITSn / 128; i++) {
        float4 a = row[lane + i * 32];
        float4 b = v4[lane + i * 32];
        acc += a.x * b.x + a.y * b.y + a.z * b.z + a.w * b.w;
    }
#pragma unroll
    for (int o = 16; o; o >>= 1) acc += __shfl_xor_sync(0xffffffffu, acc, o);
    if (lane == 0) g_w[warp] = acc;
}

// ---------------------------------------------------------------------------
// K2: qb[b] = query[b]·w[HALF:] + b1·V + bV   (one block per batch)
// ---------------------------------------------------------------------------
__global__ __launch_bounds__(256) void k_qb(const float* __restrict__ query,
                                            const float* __restrict__ b1,
                                            const float* __restrict__ V,
                                            const float* __restrict__ bV) {
    int b = blockIdx.x;
    int tid = threadIdx.x, warp = tid >> 5, lane = tid & 31;
    __shared__ float red[8];

    // 256 float4 cover DQn=1024
    float4 q = reinterpret_cast<const float4*>(query + (size_t)b * DQn)[tid];
    float4 w = reinterpret_cast<const float4*>(g_w + HALFn)[tid];
    float4 bb = reinterpret_cast<const float4*>(b1)[tid];
    float4 vv = reinterpret_cast<const float4*>(V)[tid];
    float acc = q.x * w.x + q.y * w.y + q.z * w.z + q.w * w.w
              + bb.x * vv.x + bb.y * vv.y + bb.z * vv.z + bb.w * vv.w;
#pragma unroll
    for (int o = 16; o; o >>= 1) acc += __shfl_xor_sync(0xffffffffu, acc, o);
    if (lane == 0) red[warp] = acc;
    __syncthreads();
    if (tid == 0) {
        float s = 0.f;
#pragma unroll
        for (int i = 0; i < 8; i++) s += red[i];
        g_qb[b] = s + bV[0];
    }
}

// ---------------------------------------------------------------------------
// K3 (k_main): single-pass fused attention, warp-pair specialized.
//   Even warp (A): cols 0-1023  — loads, dot, softmax state, first-half acc.
//   Odd  warp (B): cols 1024-2047 — prefetches loads, waits on pair barrier,
//                                   applies (e,c) from A, second-half acc.
//   No block barriers in the streaming loop; every byte read exactly once.
// ---------------------------------------------------------------------------
__global__ __launch_bounds__(256, 2) void k_main(const float* __restrict__ values) {
    __shared__ float sw[HALFn];                   // 4 KB: w[:1024]
    __shared__ float s_e[2][PAIRS], s_c[2][PAIRS];
    __shared__ float s_m[PAIRS], s_Z[PAIRS];
    __shared__ float swacc[PAIRS * HALFn];        // 16 KB merge buffer

    int seg = blockIdx.x, b = blockIdx.y;
    int tid = threadIdx.x, warp = tid >> 5, lane = tid & 31;
    int pair = warp >> 1;
    bool isA = (warp & 1) == 0;
    int barid = 1 + pair;

    for (int i = tid; i < HALFn; i += 256) sw[i] = g_w[i];
    float qb = g_qb[b];
    __syncthreads();

    int tbase = seg * TS;
    const float* base = values + ((size_t)(b * Tn + tbase)) * Fn;
    const float4* w4 = reinterpret_cast<const float4*>(sw);

    float4 acc[8];
#pragma unroll
    for (int i = 0; i < 8; i++) acc[i] = make_float4(0.f, 0.f, 0.f, 0.f);
    float m = -1e30f, Z = 0.f;

    if (isA) {
#pragma unroll 1
        for (int r = 0; r < RPP; r++) {
            int row = r * PAIRS + pair;
            const float4* rp = reinterpret_cast<const float4*>(base + (size_t)row * Fn);
            float4 v[8];
#pragma unroll
            for (int i = 0; i < 8; i++) v[i] = rp[lane + 32 * i];
            float d = 0.f;
#pragma unroll
            for (int i = 0; i < 8; i++) {
                float4 w = w4[lane + 32 * i];
                d += v[i].x * w.x + v[i].y * w.y + v[i].z * w.z + v[i].w * w.w;
            }
#pragma unroll
            for (int o = 16; o; o >>= 1) d += __shfl_xor_sync(0xffffffffu, d, o);
            float s = d + qb;
            if (lane == 0) g_score[b * Tn + tbase + row] = s;

            float c = 1.f;
            if (s > m) {                 // warp-uniform
                c = __expf(m - s);
                m = s;
                Z *= c;
            }
            float e = __expf(s - m);
            Z += e;
            if (lane == 0) { s_e[r & 1][pair] = e; s_c[r & 1][pair] = c; }
            asm volatile("bar.sync %0, 64;" :: "r"(barid) : "memory");

            if (c != 1.f) {
#pragma unroll
                for (int i = 0; i < 8; i++) {
                    acc[i].x *= c; acc[i].y *= c; acc[i].z *= c; acc[i].w *= c;
                }
            }
#pragma unroll
            for (int i = 0; i < 8; i++) {
                acc[i].x += e * v[i].x; acc[i].y += e * v[i].y;
                acc[i].z += e * v[i].z; acc[i].w += e * v[i].w;
            }
        }
        if (lane == 0) { s_m[pair] = m; s_Z[pair] = Z; }
    } else {
#pragma unroll 1
        for (int r = 0; r < RPP; r++) {
            int row = r * PAIRS + pair;
            const float4* rp = reinterpret_cast<const float4*>(
                base + (size_t)row * Fn + HALFn);
            float4 v[8];
#pragma unroll
            for (int i = 0; i < 8; i++) v[i] = rp[lane + 32 * i];   // overlap A's chain
            asm volatile("bar.sync %0, 64;" :: "r"(barid) : "memory");
            float e = s_e[r & 1][pair];
            float c = s_c[r & 1][pair];
            if (c != 1.f) {
#pragma unroll
                for (int i = 0; i < 8; i++) {
                    acc[i].x *= c; acc[i].y *= c; acc[i].z *= c; acc[i].w *= c;
                }
            }
#pragma unroll
            for (int i = 0; i < 8; i++) {
                acc[i].x += e * v[i].x; acc[i].y += e * v[i].y;
                acc[i].z += e * v[i].z; acc[i].w += e * v[i].w;
            }
        }
    }
    __syncthreads();

    // ---- merge 4 pairs ----
    float mseg = s_m[0];
#pragma unroll
    for (int p = 1; p < PAIRS; p++) mseg = fmaxf(mseg, s_m[p]);
    float wt[PAIRS];
    float Zseg = 0.f;
#pragma unroll
    for (int p = 0; p < PAIRS; p++) {
        wt[p] = __expf(s_m[p] - mseg);
        Zseg += s_Z[p] * wt[p];
    }

    float* part = g_partial + ((size_t)(b * SEG + seg)) * Fn;

    // first half: A warps dump, all threads reduce
    if (isA) {
#pragma unroll
        for (int i = 0; i < 8; i++)
            *reinterpret_cast<float4*>(&swacc[pair * HALFn + 4 * (lane + 32 * i)]) = acc[i];
    }
    __syncthreads();
    {
        float4 r = make_float4(0.f, 0.f, 0.f, 0.f);
#pragma unroll
        for (int p = 0; p < PAIRS; p++) {
            float4 c = *reinterpret_cast<const float4*>(&swacc[p * HALFn + 4 * tid]);
            r.x += wt[p] * c.x; r.y += wt[p] * c.y;
            r.z += wt[p] * c.z; r.w += wt[p] * c.w;
        }
        *reinterpret_cast<float4*>(&part[4 * tid]) = r;
    }
    __syncthreads();
    // second half: B warps dump, all threads reduce
    if (!isA) {
#pragma unroll
        for (int i = 0; i < 8; i++)
            *reinterpret_cast<float4*>(&swacc[pair * HALFn + 4 * (lane + 32 * i)]) = acc[i];
    }
    __syncthreads();
    {
        float4 r = make_float4(0.f, 0.f, 0.f, 0.f);
#pragma unroll
        for (int p = 0; p < PAIRS; p++) {
            float4 c = *reinterpret_cast<const float4*>(&swacc[p * HALFn + 4 * tid]);
            r.x += wt[p] * c.x; r.y += wt[p] * c.y;
            r.z += wt[p] * c.z; r.w += wt[p] * c.w;
        }
        *reinterpret_cast<float4*>(&part[HALFn + 4 * tid]) = r;
    }

    if (tid == 0) {
        g_m[b * SEG + seg] = mseg;
        g_Z[b * SEG + seg] = Zseg;
    }
}

// ---------------------------------------------------------------------------
// K4 (k_epi): grid (Bn, 4), 256 threads.
//   y 0..1: context half y   y 2..3: attention-weight half (y-2)
// ---------------------------------------------------------------------------
__global__ __launch_bounds__(256) void k_epi(float* __restrict__ ctx,
                                             float* __restrict__ aw) {
    int b = blockIdx.x;
    int tid = threadIdx.x;
    int y = blockIdx.y;

    float gm = -1e30f;
#pragma unroll
    for (int s = 0; s < SEG; s++) gm = fmaxf(gm, g_m[b * SEG + s]);
    float Zg = 0.f;
#pragma unroll
    for (int s = 0; s < SEG; s++) Zg += g_Z[b * SEG + s] * __expf(g_m[b * SEG + s] - gm);
    float inv = 1.0f / Zg;

    if (y < 2) {
        // context half y: cols [y*1024 + 4*tid ...]
        int col = y * HALFn + 4 * tid;
        float4 a = make_float4(0.f, 0.f, 0.f, 0.f);
#pragma unroll
        for (int s = 0; s < SEG; s++) {
            float w = __expf(g_m[b * SEG + s] - gm) * inv;
            float4 c = *reinterpret_cast<const float4*>(
                &g_partial[((size_t)(b * SEG + s)) * Fn + col]);
            a.x += w * c.x; a.y += w * c.y; a.z += w * c.z; a.w += w * c.w;
        }
        *reinterpret_cast<float4*>(&ctx[(size_t)b * Fn + col]) = a;
    } else {
        int off = (y - 2) * (Tn / 2) + 4 * tid;
        float4 sc = *reinterpret_cast<const float4*>(&g_score[b * Tn + off]);
        float4 r;
        r.x = __expf(sc.x - gm) * inv;
        r.y = __expf(sc.y - gm) * inv;
        r.z = __expf(sc.z - gm) * inv;
        r.w = __expf(sc.w - gm) * inv;
        *reinterpret_cast<float4*>(&aw[b * Tn + off]) = r;
    }
}

// ---------------------------------------------------------------------------
extern "C" void kernel_launch(void* const* d_in, const int* in_sizes, int n_in,
                              void* d_out, int out_size) {
    const float* query  = (const float*)d_in[0];
    const float* values = (const float*)d_in[1];
    const float* W1     = (const float*)d_in[2];
    const float* b1     = (const float*)d_in[3];
    const float* V      = (const float*)d_in[4];
    const float* bV     = (const float*)d_in[5];

    float* out = (float*)d_out;
    float* ctx = out;                 // [B, F]   context_vector (32,1,2048)
    float* aw  = out + Bn * Fn;       // [B, T]   attention_weights (32,2048,1)

    k_w<<<CONCATn / 8, 256>>>(W1, V);
    k_qb<<<Bn, 256>>>(query, b1, V, bV);
    dim3 g(SEG, Bn);
    k_main<<<g, 256>>>(values);
    dim3 ge(Bn, 4);
    k_epi<<<ge, 256>>>(ctx, aw);
}

// round 7
// speedup vs baseline: 1.2070x; 1.0023x over previous
#include <cuda_runtime.h>

#define Bn 32
#define Tn 2048
#define Fn 2048
#define DQn 1024
#define UNITSn 1024
#define HALFn 1024      // F/2
#define CONCATn 2048    // HALF + DQ
#define SEG 16          // T segments per batch
#define TS (Tn / SEG)   // 128 rows per segment block
#define PAIRS 4         // warp pairs per block (8 warps, 256 threads)
#define RPP (TS / PAIRS) // 32 rows per pair

// Scratch (allocation-free rule: __device__ globals)
__device__ float g_w[CONCATn];               // W1 @ V
__device__ float g_bias;                     // b1·V + bV
__device__ float g_score[Bn * Tn];           // raw scores
__device__ float g_partial[Bn * SEG * Fn];   // per-seg ctx partials (scale e^{m_seg})
__device__ float g_m[Bn * SEG];              // per-segment max
__device__ float g_Z[Bn * SEG];              // per-segment exp-sum at m_seg
__device__ int   g_cnt[Bn];                  // per-batch arrival counter (self-resetting)

// ---------------------------------------------------------------------------
// K1: w[c] = sum_u W1[c,u] * V[u]  (warp per c); last block: bias = b1·V + bV
// ---------------------------------------------------------------------------
__global__ void k_w(const float* __restrict__ W1, const float* __restrict__ V,
                    const float* __restrict__ b1, const float* __restrict__ bV) {
    if (blockIdx.x == CONCATn / 8) {
        if (threadIdx.x < 32) {
            int lane = threadIdx.x;
            const float4* b4 = reinterpret_cast<const float4*>(b1);
            const float4* v4 = reinterpret_cast<const float4*>(V);
            float acc = 0.f;
#pragma unroll
            for (int i = 0; i < UNITSn / 128; i++) {
                float4 a = b4[lane + i * 32];
                float4 b = v4[lane + i * 32];
                acc += a.x * b.x + a.y * b.y + a.z * b.z + a.w * b.w;
            }
#pragma unroll
            for (int o = 16; o; o >>= 1) acc += __shfl_xor_sync(0xffffffffu, acc, o);
            if (lane == 0) g_bias = acc + bV[0];
        }
        return;
    }
    int warp = blockIdx.x * 8 + (threadIdx.x >> 5);
    int lane = threadIdx.x & 31;
    const float4* row = reinterpret_cast<const float4*>(W1 + (size_t)warp * UNITSn);
    const float4* v4  = reinterpret_cast<const float4*>(V);
    float acc = 0.f;
#pragma unroll
    for (int i = 0; i < UNITSn / 128; i++) {
        float4 a = row[lane + i * 32];
        float4 b = v4[lane + i * 32];
        acc += a.x * b.x + a.y * b.y + a.z * b.z + a.w * b.w;
    }
#pragma unroll
    for (int o = 16; o; o >>= 1) acc += __shfl_xor_sync(0xffffffffu, acc, o);
    if (lane == 0) g_w[warp] = acc;
}

// ---------------------------------------------------------------------------
// K2 (k_main): single-pass fused attention, warp-pair specialized, with
//   fused qb prologue and fused combine epilogue (threadfence reduction).
// ---------------------------------------------------------------------------
__global__ __launch_bounds__(256, 2) void k_main(const float* __restrict__ values,
                                                 const float* __restrict__ query,
                                                 float* __restrict__ ctx,
                                                 float* __restrict__ aw) {
    __shared__ float sw[HALFn];                   // 4 KB: w[:1024]
    __shared__ float s_e[2][PAIRS], s_c[2][PAIRS];
    __shared__ float s_m[PAIRS], s_Z[PAIRS];
    __shared__ float swacc[PAIRS * HALFn];        // 16 KB merge buffer
    __shared__ float red[8];
    __shared__ int   s_last;

    int seg = blockIdx.x, b = blockIdx.y;
    int tid = threadIdx.x, warp = tid >> 5, lane = tid & 31;
    int pair = warp >> 1;
    bool isA = (warp & 1) == 0;
    int barid = 1 + pair;

    // ---- prologue: load w, compute qb = query[b]·w[1024:] + bias ----
    for (int i = tid; i < HALFn; i += 256) sw[i] = g_w[i];
    {
        float4 q = reinterpret_cast<const float4*>(query + (size_t)b * DQn)[tid];
        float4 w = reinterpret_cast<const float4*>(g_w + HALFn)[tid];
        float p = q.x * w.x + q.y * w.y + q.z * w.z + q.w * w.w;
#pragma unroll
        for (int o = 16; o; o >>= 1) p += __shfl_xor_sync(0xffffffffu, p, o);
        if (lane == 0) red[warp] = p;
    }
    __syncthreads();
    float qb = g_bias;
#pragma unroll
    for (int i = 0; i < 8; i++) qb += red[i];

    int tbase = seg * TS;
    const float* base = values + ((size_t)(b * Tn + tbase)) * Fn;
    const float4* w4 = reinterpret_cast<const float4*>(sw);

    float4 acc[8];
#pragma unroll
    for (int i = 0; i < 8; i++) acc[i] = make_float4(0.f, 0.f, 0.f, 0.f);
    float m = -1e30f, Z = 0.f;

    if (isA) {
#pragma unroll 1
        for (int r = 0; r < RPP; r++) {
            int row = r * PAIRS + pair;
            const float4* rp = reinterpret_cast<const float4*>(base + (size_t)row * Fn);
            float4 v[8];
#pragma unroll
            for (int i = 0; i < 8; i++) v[i] = rp[lane + 32 * i];
            float d = 0.f;
#pragma unroll
            for (int i = 0; i < 8; i++) {
                float4 w = w4[lane + 32 * i];
                d += v[i].x * w.x + v[i].y * w.y + v[i].z * w.z + v[i].w * w.w;
            }
#pragma unroll
            for (int o = 16; o; o >>= 1) d += __shfl_xor_sync(0xffffffffu, d, o);
            float s = d + qb;
            if (lane == 0) g_score[b * Tn + tbase + row] = s;

            float c = 1.f;
            if (s > m) {                 // warp-uniform
                c = __expf(m - s);
                m = s;
                Z *= c;
            }
            float e = __expf(s - m);
            Z += e;
            if (lane == 0) { s_e[r & 1][pair] = e; s_c[r & 1][pair] = c; }
            asm volatile("bar.sync %0, 64;" :: "r"(barid) : "memory");

            if (c != 1.f) {
#pragma unroll
                for (int i = 0; i < 8; i++) {
                    acc[i].x *= c; acc[i].y *= c; acc[i].z *= c; acc[i].w *= c;
                }
            }
#pragma unroll
            for (int i = 0; i < 8; i++) {
                acc[i].x += e * v[i].x; acc[i].y += e * v[i].y;
                acc[i].z += e * v[i].z; acc[i].w += e * v[i].w;
            }
        }
        if (lane == 0) { s_m[pair] = m; s_Z[pair] = Z; }
    } else {
#pragma unroll 1
        for (int r = 0; r < RPP; r++) {
            int row = r * PAIRS + pair;
            const float4* rp = reinterpret_cast<const float4*>(
                base + (size_t)row * Fn + HALFn);
            float4 v[8];
#pragma unroll
            for (int i = 0; i < 8; i++) v[i] = rp[lane + 32 * i];   // overlap A's chain
            asm volatile("bar.sync %0, 64;" :: "r"(barid) : "memory");
            float e = s_e[r & 1][pair];
            float c = s_c[r & 1][pair];
            if (c != 1.f) {
#pragma unroll
                for (int i = 0; i < 8; i++) {
                    acc[i].x *= c; acc[i].y *= c; acc[i].z *= c; acc[i].w *= c;
                }
            }
#pragma unroll
            for (int i = 0; i < 8; i++) {
                acc[i].x += e * v[i].x; acc[i].y += e * v[i].y;
                acc[i].z += e * v[i].z; acc[i].w += e * v[i].w;
            }
        }
    }
    __syncthreads();

    // ---- merge 4 pairs into segment partial ----
    float mseg = s_m[0];
#pragma unroll
    for (int p = 1; p < PAIRS; p++) mseg = fmaxf(mseg, s_m[p]);
    float wt[PAIRS];
    float Zseg = 0.f;
#pragma unroll
    for (int p = 0; p < PAIRS; p++) {
        wt[p] = __expf(s_m[p] - mseg);
        Zseg += s_Z[p] * wt[p];
    }

    float* part = g_partial + ((size_t)(b * SEG + seg)) * Fn;

    if (isA) {
#pragma unroll
        for (int i = 0; i < 8; i++)
            *reinterpret_cast<float4*>(&swacc[pair * HALFn + 4 * (lane + 32 * i)]) = acc[i];
    }
    __syncthreads();
    {
        float4 r = make_float4(0.f, 0.f, 0.f, 0.f);
#pragma unroll
        for (int p = 0; p < PAIRS; p++) {
            float4 c = *reinterpret_cast<const float4*>(&swacc[p * HALFn + 4 * tid]);
            r.x += wt[p] * c.x; r.y += wt[p] * c.y;
            r.z += wt[p] * c.z; r.w += wt[p] * c.w;
        }
        *reinterpret_cast<float4*>(&part[4 * tid]) = r;
    }
    __syncthreads();
    if (!isA) {
#pragma unroll
        for (int i = 0; i < 8; i++)
            *reinterpret_cast<float4*>(&swacc[pair * HALFn + 4 * (lane + 32 * i)]) = acc[i];
    }
    __syncthreads();
    {
        float4 r = make_float4(0.f, 0.f, 0.f, 0.f);
#pragma unroll
        for (int p = 0; p < PAIRS; p++) {
            float4 c = *reinterpret_cast<const float4*>(&swacc[p * HALFn + 4 * tid]);
            r.x += wt[p] * c.x; r.y += wt[p] * c.y;
            r.z += wt[p] * c.z; r.w += wt[p] * c.w;
        }
        *reinterpret_cast<float4*>(&part[HALFn + 4 * tid]) = r;
    }

    if (tid == 0) {
        g_m[b * SEG + seg] = mseg;
        g_Z[b * SEG + seg] = Zseg;
    }

    // ---- fused epilogue: last-arriving block per batch combines ----
    __threadfence();
    __syncthreads();
    if (tid == 0) {
        int prev = atomicAdd(&g_cnt[b], 1);
        s_last = (prev == SEG - 1);
    }
    __syncthreads();
    if (!s_last) return;
    __threadfence();   // acquire side: partials/scores from peer blocks

    float gm = -1e30f;
#pragma unroll
    for (int s = 0; s < SEG; s++) gm = fmaxf(gm, g_m[b * SEG + s]);
    float Zg = 0.f;
#pragma unroll
    for (int s = 0; s < SEG; s++) Zg += g_Z[b * SEG + s] * __expf(g_m[b * SEG + s] - gm);
    float inv = 1.0f / Zg;

    // context: thread tid owns cols 4*tid and 1024+4*tid
    float4 c0 = make_float4(0.f, 0.f, 0.f, 0.f);
    float4 c1 = make_float4(0.f, 0.f, 0.f, 0.f);
#pragma unroll
    for (int s = 0; s < SEG; s++) {
        float w = __expf(g_m[b * SEG + s] - gm) * inv;
        const float* ps = g_partial + ((size_t)(b * SEG + s)) * Fn;
        float4 p0 = *reinterpret_cast<const float4*>(&ps[4 * tid]);
        float4 p1 = *reinterpret_cast<const float4*>(&ps[HALFn + 4 * tid]);
        c0.x += w * p0.x; c0.y += w * p0.y; c0.z += w * p0.z; c0.w += w * p0.w;
        c1.x += w * p1.x; c1.y += w * p1.y; c1.z += w * p1.z; c1.w += w * p1.w;
    }
    *reinterpret_cast<float4*>(&ctx[(size_t)b * Fn + 4 * tid]) = c0;
    *reinterpret_cast<float4*>(&ctx[(size_t)b * Fn + HALFn + 4 * tid]) = c1;

    // attention weights: thread tid owns t = 4*tid and 1024+4*tid
#pragma unroll
    for (int h = 0; h < 2; h++) {
        int off = h * 1024 + 4 * tid;
        float4 sc = *reinterpret_cast<const float4*>(&g_score[b * Tn + off]);
        float4 r;
        r.x = __expf(sc.x - gm) * inv;
        r.y = __expf(sc.y - gm) * inv;
        r.z = __expf(sc.z - gm) * inv;
        r.w = __expf(sc.w - gm) * inv;
        *reinterpret_cast<float4*>(&aw[b * Tn + off]) = r;
    }

    if (tid == 0) g_cnt[b] = 0;   // reset for next graph replay
}

// ---------------------------------------------------------------------------
extern "C" void kernel_launch(void* const* d_in, const int* in_sizes, int n_in,
                              void* d_out, int out_size) {
    const float* query  = (const float*)d_in[0];
    const float* values = (const float*)d_in[1];
    const float* W1     = (const float*)d_in[2];
    const float* b1     = (const float*)d_in[3];
    const float* V      = (const float*)d_in[4];
    const float* bV     = (const float*)d_in[5];

    float* out = (float*)d_out;
    float* ctx = out;                 // [B, F]   context_vector (32,1,2048)
    float* aw  = out + Bn * Fn;       // [B, T]   attention_weights (32,2048,1)

    k_w<<<CONCATn / 8 + 1, 256>>>(W1, V, b1, bV);
    dim3 g(SEG, Bn);
    k_main<<<g, 256>>>(values, query, ctx, aw);
}

// round 8
// speedup vs baseline: 1.2398x; 1.0272x over previous
#include <cuda_runtime.h>

#define Bn 32
#define Tn 2048
#define Fn 2048
#define DQn 1024
#define UNITSn 1024
#define HALFn 1024      // F/2
#define CONCATn 2048    // HALF + DQ
#define SEG 8           // T segments per batch -> grid 256 = single wave
#define TS (Tn / SEG)   // 256 rows per segment block
#define PAIRS 4         // warp pairs per block (8 warps, 256 threads)
#define RPP (TS / PAIRS) // 64 rows per pair

// Scratch (allocation-free rule: __device__ globals)
__device__ float g_w[CONCATn];               // W1 @ V
__device__ float g_bias;                     // b1·V + bV
__device__ float g_score[Bn * Tn];           // raw scores
__device__ float g_partial[Bn * SEG * Fn];   // per-seg ctx partials (scale e^{m_seg})
__device__ float g_m[Bn * SEG];              // per-segment max
__device__ float g_Z[Bn * SEG];              // per-segment exp-sum at m_seg
__device__ int   g_cnt[Bn];                  // per-batch arrival counter (self-resetting)

// ---------------------------------------------------------------------------
// K1: w[c] = sum_u W1[c,u] * V[u]  (warp per c); last block: bias = b1·V + bV
// ---------------------------------------------------------------------------
__global__ void k_w(const float* __restrict__ W1, const float* __restrict__ V,
                    const float* __restrict__ b1, const float* __restrict__ bV) {
    if (blockIdx.x == CONCATn / 8) {
        if (threadIdx.x < 32) {
            int lane = threadIdx.x;
            const float4* b4 = reinterpret_cast<const float4*>(b1);
            const float4* v4 = reinterpret_cast<const float4*>(V);
            float acc = 0.f;
#pragma unroll
            for (int i = 0; i < UNITSn / 128; i++) {
                float4 a = b4[lane + i * 32];
                float4 b = v4[lane + i * 32];
                acc += a.x * b.x + a.y * b.y + a.z * b.z + a.w * b.w;
            }
#pragma unroll
            for (int o = 16; o; o >>= 1) acc += __shfl_xor_sync(0xffffffffu, acc, o);
            if (lane == 0) g_bias = acc + bV[0];
        }
        return;
    }
    int warp = blockIdx.x * 8 + (threadIdx.x >> 5);
    int lane = threadIdx.x & 31;
    const float4* row = reinterpret_cast<const float4*>(W1 + (size_t)warp * UNITSn);
    const float4* v4  = reinterpret_cast<const float4*>(V);
    float acc = 0.f;
#pragma unroll
    for (int i = 0; i < UNITSn / 128; i++) {
        float4 a = row[lane + i * 32];
        float4 b = v4[lane + i * 32];
        acc += a.x * b.x + a.y * b.y + a.z * b.z + a.w * b.w;
    }
#pragma unroll
    for (int o = 16; o; o >>= 1) acc += __shfl_xor_sync(0xffffffffu, acc, o);
    if (lane == 0) g_w[warp] = acc;
}

// ---------------------------------------------------------------------------
// K2 (k_main): single-pass fused attention, warp-pair specialized.
//   grid (SEG=8, Bn=32) = 256 blocks -> SINGLE wave at 2 CTAs/SM.
//   Even warp (A): cols 0-1023 — loads, dot, softmax state, first-half acc.
//   Odd  warp (B): cols 1024-2047 — prefetch, pair barrier, apply (e,c).
//   Fused qb prologue + threadfence-reduction combine epilogue.
// ---------------------------------------------------------------------------
__global__ __launch_bounds__(256, 2) void k_main(const float* __restrict__ values,
                                                 const float* __restrict__ query,
                                                 float* __restrict__ ctx,
                                                 float* __restrict__ aw) {
    __shared__ float sw[HALFn];                   // 4 KB: w[:1024]
    __shared__ float s_e[2][PAIRS], s_c[2][PAIRS];
    __shared__ float s_m[PAIRS], s_Z[PAIRS];
    __shared__ float swacc[PAIRS * HALFn];        // 16 KB merge buffer
    __shared__ float red[8];
    __shared__ int   s_last;

    int seg = blockIdx.x, b = blockIdx.y;
    int tid = threadIdx.x, warp = tid >> 5, lane = tid & 31;
    int pair = warp >> 1;
    bool isA = (warp & 1) == 0;
    int barid = 1 + pair;

    // ---- prologue: load w, compute qb = query[b]·w[1024:] + bias ----
    for (int i = tid; i < HALFn; i += 256) sw[i] = g_w[i];
    {
        float4 q = reinterpret_cast<const float4*>(query + (size_t)b * DQn)[tid];
        float4 w = reinterpret_cast<const float4*>(g_w + HALFn)[tid];
        float p = q.x * w.x + q.y * w.y + q.z * w.z + q.w * w.w;
#pragma unroll
        for (int o = 16; o; o >>= 1) p += __shfl_xor_sync(0xffffffffu, p, o);
        if (lane == 0) red[warp] = p;
    }
    __syncthreads();
    float qb = g_bias;
#pragma unroll
    for (int i = 0; i < 8; i++) qb += red[i];

    int tbase = seg * TS;
    const float* base = values + ((size_t)(b * Tn + tbase)) * Fn;
    const float4* w4 = reinterpret_cast<const float4*>(sw);

    float4 acc[8];
#pragma unroll
    for (int i = 0; i < 8; i++) acc[i] = make_float4(0.f, 0.f, 0.f, 0.f);
    float m = -1e30f, Z = 0.f;

    if (isA) {
#pragma unroll 1
        for (int r = 0; r < RPP; r++) {
            int row = r * PAIRS + pair;
            const float4* rp = reinterpret_cast<const float4*>(base + (size_t)row * Fn);
            float4 v[8];
#pragma unroll
            for (int i = 0; i < 8; i++) v[i] = rp[lane + 32 * i];
            float d = 0.f;
#pragma unroll
            for (int i = 0; i < 8; i++) {
                float4 w = w4[lane + 32 * i];
                d += v[i].x * w.x + v[i].y * w.y + v[i].z * w.z + v[i].w * w.w;
            }
#pragma unroll
            for (int o = 16; o; o >>= 1) d += __shfl_xor_sync(0xffffffffu, d, o);
            float s = d + qb;
            if (lane == 0) g_score[b * Tn + tbase + row] = s;

            float c = 1.f;
            if (s > m) {                 // warp-uniform
                c = __expf(m - s);
                m = s;
                Z *= c;
            }
            float e = __expf(s - m);
            Z += e;
            if (lane == 0) { s_e[r & 1][pair] = e; s_c[r & 1][pair] = c; }
            asm volatile("bar.sync %0, 64;" :: "r"(barid) : "memory");

            if (c != 1.f) {
#pragma unroll
                for (int i = 0; i < 8; i++) {
                    acc[i].x *= c; acc[i].y *= c; acc[i].z *= c; acc[i].w *= c;
                }
            }
#pragma unroll
            for (int i = 0; i < 8; i++) {
                acc[i].x += e * v[i].x; acc[i].y += e * v[i].y;
                acc[i].z += e * v[i].z; acc[i].w += e * v[i].w;
            }
        }
        if (lane == 0) { s_m[pair] = m; s_Z[pair] = Z; }
    } else {
#pragma unroll 1
        for (int r = 0; r < RPP; r++) {
            int row = r * PAIRS + pair;
            const float4* rp = reinterpret_cast<const float4*>(
                base + (size_t)row * Fn + HALFn);
            float4 v[8];
#pragma unroll
            for (int i = 0; i < 8; i++) v[i] = rp[lane + 32 * i];   // overlap A's chain
            asm volatile("bar.sync %0, 64;" :: "r"(barid) : "memory");
            float e = s_e[r & 1][pair];
            float c = s_c[r & 1][pair];
            if (c != 1.f) {
#pragma unroll
                for (int i = 0; i < 8; i++) {
                    acc[i].x *= c; acc[i].y *= c; acc[i].z *= c; acc[i].w *= c;
                }
            }
#pragma unroll
            for (int i = 0; i < 8; i++) {
                acc[i].x += e * v[i].x; acc[i].y += e * v[i].y;
                acc[i].z += e * v[i].z; acc[i].w += e * v[i].w;
            }
        }
    }
    __syncthreads();

    // ---- merge 4 pairs into segment partial ----
    float mseg = s_m[0];
#pragma unroll
    for (int p = 1; p < PAIRS; p++) mseg = fmaxf(mseg, s_m[p]);
    float wt[PAIRS];
    float Zseg = 0.f;
#pragma unroll
    for (int p = 0; p < PAIRS; p++) {
        wt[p] = __expf(s_m[p] - mseg);
        Zseg += s_Z[p] * wt[p];
    }

    float* part = g_partial + ((size_t)(b * SEG + seg)) * Fn;

    if (isA) {
#pragma unroll
        for (int i = 0; i < 8; i++)
            *reinterpret_cast<float4*>(&swacc[pair * HALFn + 4 * (lane + 32 * i)]) = acc[i];
    }
    __syncthreads();
    {
        float4 r = make_float4(0.f, 0.f, 0.f, 0.f);
#pragma unroll
        for (int p = 0; p < PAIRS; p++) {
            float4 c = *reinterpret_cast<const float4*>(&swacc[p * HALFn + 4 * tid]);
            r.x += wt[p] * c.x; r.y += wt[p] * c.y;
            r.z += wt[p] * c.z; r.w += wt[p] * c.w;
        }
        *reinterpret_cast<float4*>(&part[4 * tid]) = r;
    }
    __syncthreads();
    if (!isA) {
#pragma unroll
        for (int i = 0; i < 8; i++)
            *reinterpret_cast<float4*>(&swacc[pair * HALFn + 4 * (lane + 32 * i)]) = acc[i];
    }
    __syncthreads();
    {
        float4 r = make_float4(0.f, 0.f, 0.f, 0.f);
#pragma unroll
        for (int p = 0; p < PAIRS; p++) {
            float4 c = *reinterpret_cast<const float4*>(&swacc[p * HALFn + 4 * tid]);
            r.x += wt[p] * c.x; r.y += wt[p] * c.y;
            r.z += wt[p] * c.z; r.w += wt[p] * c.w;
        }
        *reinterpret_cast<float4*>(&part[HALFn + 4 * tid]) = r;
    }

    if (tid == 0) {
        g_m[b * SEG + seg] = mseg;
        g_Z[b * SEG + seg] = Zseg;
    }

    // ---- fused epilogue: last-arriving block per batch combines ----
    __threadfence();
    __syncthreads();
    if (tid == 0) {
        int prev = atomicAdd(&g_cnt[b], 1);
        s_last = (prev == SEG - 1);
    }
    __syncthreads();
    if (!s_last) return;
    __threadfence();   // acquire side: partials/scores from peer blocks

    float gm = -1e30f;
#pragma unroll
    for (int s = 0; s < SEG; s++) gm = fmaxf(gm, g_m[b * SEG + s]);
    float Zg = 0.f;
#pragma unroll
    for (int s = 0; s < SEG; s++) Zg += g_Z[b * SEG + s] * __expf(g_m[b * SEG + s] - gm);
    float inv = 1.0f / Zg;

    // context: thread tid owns cols 4*tid and 1024+4*tid
    float4 c0 = make_float4(0.f, 0.f, 0.f, 0.f);
    float4 c1 = make_float4(0.f, 0.f, 0.f, 0.f);
#pragma unroll
    for (int s = 0; s < SEG; s++) {
        float w = __expf(g_m[b * SEG + s] - gm) * inv;
        const float* ps = g_partial + ((size_t)(b * SEG + s)) * Fn;
        float4 p0 = *reinterpret_cast<const float4*>(&ps[4 * tid]);
        float4 p1 = *reinterpret_cast<const float4*>(&ps[HALFn + 4 * tid]);
        c0.x += w * p0.x; c0.y += w * p0.y; c0.z += w * p0.z; c0.w += w * p0.w;
        c1.x += w * p1.x; c1.y += w * p1.y; c1.z += w * p1.z; c1.w += w * p1.w;
    }
    *reinterpret_cast<float4*>(&ctx[(size_t)b * Fn + 4 * tid]) = c0;
    *reinterpret_cast<float4*>(&ctx[(size_t)b * Fn + HALFn + 4 * tid]) = c1;

    // attention weights: thread tid owns t = 4*tid and 1024+4*tid
#pragma unroll
    for (int h = 0; h < 2; h++) {
        int off = h * 1024 + 4 * tid;
        float4 sc = *reinterpret_cast<const float4*>(&g_score[b * Tn + off]);
        float4 r;
        r.x = __expf(sc.x - gm) * inv;
        r.y = __expf(sc.y - gm) * inv;
        r.z = __expf(sc.z - gm) * inv;
        r.w = __expf(sc.w - gm) * inv;
        *reinterpret_cast<float4*>(&aw[b * Tn + off]) = r;
    }

    if (tid == 0) g_cnt[b] = 0;   // reset for next graph replay
}

// ---------------------------------------------------------------------------
extern "C" void kernel_launch(void* const* d_in, const int* in_sizes, int n_in,
                              void* d_out, int out_size) {
    const float* query  = (const float*)d_in[0];
    const float* values = (const float*)d_in[1];
    const float* W1     = (const float*)d_in[2];
    const float* b1     = (const float*)d_in[3];
    const float* V      = (const float*)d_in[4];
    const float* bV     = (const float*)d_in[5];

    float* out = (float*)d_out;
    float* ctx = out;                 // [B, F]   context_vector (32,1,2048)
    float* aw  = out + Bn * Fn;       // [B, T]   attention_weights (32,2048,1)

    k_w<<<CONCATn / 8 + 1, 256>>>(W1, V, b1, bV);
    dim3 g(SEG, Bn);
    k_main<<<g, 256>>>(values, query, ctx, aw);
}